// round 1
// baseline (speedup 1.0000x reference)
#include <cuda_runtime.h>
#include <cstddef>

// B=128, D=1024 fixed per reference setup_inputs().
// d_in[0] = mu_in   (128*1024 f32)
// d_in[1] = Sigma_in(128*1024*1024 f32)
// d_out   = [mu_out (131072 f32) | Sigma_out (134217728 f32)]

static constexpr int B = 128;
static constexpr int D = 1024;

__global__ void rvrelu_mu_kernel(const float* __restrict__ mu,
                                 float* __restrict__ mu_out) {
    int i = blockIdx.x * blockDim.x + threadIdx.x;
    if (i < B * D) {
        float v = mu[i];
        mu_out[i] = v > 0.0f ? v : 0.0f;
    }
}

// One block per (b, i) row of Sigma. 256 threads, each handles one float4
// (4 consecutive j). mask_i is block-uniform: if mu[b,i] <= 0 the whole row
// is zero -> store zeros, skip the 4 KB load entirely (~halves read traffic).
__global__ __launch_bounds__(256) void rvrelu_sigma_kernel(
    const float4* __restrict__ Sigma,
    const float* __restrict__ mu,
    float4* __restrict__ Sigma_out) {
    const int row = blockIdx.x;          // row = b * D + i, in [0, B*D)
    const int b   = row >> 10;           // / D
    const int tid = threadIdx.x;         // 0..255, one float4 each

    const size_t base = (size_t)row * (D / 4);
    float4* dst = Sigma_out + base + tid;

    const float mi = __ldg(mu + row);    // mu[b*D + i]
    if (mi <= 0.0f) {
        *dst = make_float4(0.0f, 0.0f, 0.0f, 0.0f);
        return;
    }

    // Row is active: v * 1[mu[b,j] > 0]
    float4 v = __ldg(Sigma + base + tid);
    const float4 mrow = __ldg(reinterpret_cast<const float4*>(mu + (size_t)b * D) + tid);
    v.x = (mrow.x > 0.0f) ? v.x : 0.0f;
    v.y = (mrow.y > 0.0f) ? v.y : 0.0f;
    v.z = (mrow.z > 0.0f) ? v.z : 0.0f;
    v.w = (mrow.w > 0.0f) ? v.w : 0.0f;
    *dst = v;
}

extern "C" void kernel_launch(void* const* d_in, const int* in_sizes, int n_in,
                              void* d_out, int out_size) {
    const float* mu    = (const float*)d_in[0];
    const float* Sigma = (const float*)d_in[1];

    float* mu_out    = (float*)d_out;
    float* Sigma_out = (float*)d_out + (size_t)B * D;

    // mu_out: 131072 elems
    rvrelu_mu_kernel<<<(B * D + 255) / 256, 256>>>(mu, mu_out);

    // Sigma_out: one block per row, 131072 blocks x 256 threads
    rvrelu_sigma_kernel<<<B * D, 256>>>(
        (const float4*)Sigma, mu, (float4*)Sigma_out);
}

// round 2
// speedup vs baseline: 1.1982x; 1.1982x over previous
#include <cuda_runtime.h>
#include <cstddef>

// B=128, D=1024. d_in[0]=mu (131072 f32), d_in[1]=Sigma (128*1024*1024 f32)
// d_out = [mu_out 131072 f32 | Sigma_out 134217728 f32]

static constexpr int B = 128;
static constexpr int D = 1024;

// One block = 4 consecutive rows of Sigma (rows 4*blk .. 4*blk+3, always
// within one batch b since D % 4 == 0). 256 threads; thread t owns columns
// [4t, 4t+4) of ALL 4 rows:
//   - one float4 load gives the 4 row-masks (mu[4*blk .. 4*blk+3])
//   - one float4 load of the mu row gives the column mask, reused 4x
//   - 4 independent Sigma float4 loads (MLP=4), predicated off per-row mask
// Thread 0 also writes the relu'd mu_out for the block's 4 rows (fuses the
// old mu kernel).
__global__ __launch_bounds__(256) void rvrelu_fused_kernel(
    const float4* __restrict__ Sigma,
    const float*  __restrict__ mu,
    float4* __restrict__ Sigma_out,
    float4* __restrict__ mu_out4) {

    const int blk  = blockIdx.x;        // 0 .. 32767
    const int row0 = blk << 2;          // first of 4 rows
    const int b    = row0 >> 10;        // batch index
    const int t    = threadIdx.x;       // 0..255

    // 4 row masks in one aligned 16B load (L2/L1 hit after first touch)
    const float4 mi4 = __ldg(reinterpret_cast<const float4*>(mu) + blk);

    // fused mu_out: one relu'd float4 store per block
    if (t == 0) {
        float4 r;
        r.x = mi4.x > 0.0f ? mi4.x : 0.0f;
        r.y = mi4.y > 0.0f ? mi4.y : 0.0f;
        r.z = mi4.z > 0.0f ? mi4.z : 0.0f;
        r.w = mi4.w > 0.0f ? mi4.w : 0.0f;
        mu_out4[blk] = r;
    }

    // column mask: mu[b, 4t..4t+3], shared by all 4 rows
    const float4 mrow =
        __ldg(reinterpret_cast<const float4*>(mu + (size_t)b * D) + t);

    const float mis[4] = {mi4.x, mi4.y, mi4.z, mi4.w};
    const size_t base = (size_t)row0 * (D / 4) + t;   // float4 index

    // Phase 1: issue all 4 independent Sigma loads (predicated) -> MLP=4
    float4 v[4];
#pragma unroll
    for (int r = 0; r < 4; r++) {
        if (mis[r] > 0.0f) {
            v[r] = __ldg(Sigma + base + (size_t)r * (D / 4));
        } else {
            v[r] = make_float4(0.0f, 0.0f, 0.0f, 0.0f);
        }
    }

    // Phase 2: apply column mask and store
#pragma unroll
    for (int r = 0; r < 4; r++) {
        float4 o = v[r];
        o.x = mrow.x > 0.0f ? o.x : 0.0f;
        o.y = mrow.y > 0.0f ? o.y : 0.0f;
        o.z = mrow.z > 0.0f ? o.z : 0.0f;
        o.w = mrow.w > 0.0f ? o.w : 0.0f;
        Sigma_out[base + (size_t)r * (D / 4)] = o;
    }
}

extern "C" void kernel_launch(void* const* d_in, const int* in_sizes, int n_in,
                              void* d_out, int out_size) {
    const float* mu    = (const float*)d_in[0];
    const float* Sigma = (const float*)d_in[1];

    float4* mu_out4  = (float4*)d_out;
    float4* Sigma_out = (float4*)((float*)d_out + (size_t)B * D);

    // 32768 blocks x 256 threads; 4 Sigma rows per block
    rvrelu_fused_kernel<<<(B * D) / 4, 256>>>(
        (const float4*)Sigma, mu, Sigma_out, mu_out4);
}